// round 17
// baseline (speedup 1.0000x reference)
#include <cuda_runtime.h>
#include <cuda_bf16.h>

// NCELoss: N=4096, E=1024, K=50 noise (+1 target), V=50257. Scalar f32 loss.
//
// Inverted (bucketed) access: weight rows read ONCE into registers (203 MB),
// bf16 input streamed per sample (428 MB). R16 profile: dot is largely
// instruction-issue bound (issue 52%, fma 25.5 + alu 24.5, occ 36.5%).
// R17 shrinks the per-sample instruction stream ~30%:
//   - input loads: 4 x LDG.128 (uint4) instead of 8 x LDG.64
//   - math: packed fma.rn.f32x2 (16 FFMA2 instead of 32 FFMA); bf16->f32
//     conversion via shift/mask feeding the packed lanes directly
//   - weight row register layout re-grouped to 8-element blocks to match
//   - __launch_bounds__(128,8): 64-reg target -> 32 warps/SM
// Pipeline: prep (fused scatter + fp32->bf16 convert) -> dot (term + full
// reduction + out, self-resetting ticket). g_cnt zero at load; dot re-zeroes
// consumed rows. Atomic/bucket order only perturbs double-accumulation
// order (~ulp); rel_err ~6e-7. Graph-replay safe; no allocations.

#define EDIM    1024
#define KNOISE  50
#define NCOLS   (KNOISE + 1)
#define NORM_TERM 9.0f
#define VMAX    50260
#define NMAX    4096
#define CAP     64            // bucket capacity (Poisson mean 4.16 -> safe)
#define DOT_BLOCK 128
#define DOT_GRID  1776

typedef unsigned long long u64;

__device__ __nv_bfloat16 g_xbf[NMAX * EDIM];       // 8.4 MB bf16 input
__device__ int           g_cnt[VMAX];              // zero at load; dot re-zeroes
__device__ int           g_bucket[VMAX * CAP];     // entries: n*51+j
__device__ double        g_acc  = 0.0;             // global loss accumulator
__device__ unsigned int  g_done = 0;               // completion ticket

// Pack two f32 into a b64 (f32x2 lanes: lo, hi).
__device__ __forceinline__ u64 pack2(float a, float b) {
    u64 r; asm("mov.b64 %0, {%1, %2};" : "=l"(r) : "f"(a), "f"(b)); return r;
}
// bf16x2 (lo=elem 2m, hi=elem 2m+1) -> packed f32x2 via shift/mask.
__device__ __forceinline__ u64 cvt2(unsigned int v) {
    const unsigned int lo = v << 16;
    const unsigned int hi = v & 0xffff0000u;
    u64 r; asm("mov.b64 %0, {%1, %2};" : "=l"(r) : "r"(lo), "r"(hi)); return r;
}
// acc = a * b + acc on both f32 lanes (Blackwell FFMA2).
__device__ __forceinline__ void ffma2(u64& acc, u64 a, u64 b) {
    asm("fma.rn.f32x2 %0, %1, %2, %0;" : "+l"(acc) : "l"(a), "l"(b));
}
__device__ __forceinline__ float unpack_sum(u64 a) {
    float lo, hi;
    asm("mov.b64 {%0, %1}, %2;" : "=f"(lo), "=f"(hi) : "l"(a));
    return lo + hi;
}

// ------- A: fused scatter (bucket samples) + input fp32->bf16 convert ------
__global__ void prep_kernel(const float* __restrict__ input,
                            const int*   __restrict__ target,
                            const int*   __restrict__ noise_samples,
                            int N)
{
    const int tid    = blockIdx.x * blockDim.x + threadIdx.x;
    const int stride = gridDim.x * blockDim.x;

    const int total = N * NCOLS;
    for (int i = tid; i < total; i += stride) {
        const int n = i / NCOLS;
        const int j = i - n * NCOLS;
        const int idx = (j == 0) ? __ldg(&target[n])
                                 : __ldg(&noise_samples[n * KNOISE + (j - 1)]);
        const int slot = atomicAdd(&g_cnt[idx], 1);
        if (slot < CAP) g_bucket[idx * CAP + slot] = i;
    }

    const int nq = N * EDIM / 4;
    const float4* in4 = reinterpret_cast<const float4*>(input);
    uint2* ob = reinterpret_cast<uint2*>(g_xbf);
    for (int i = tid; i < nq; i += stride) {
        const float4 v = __ldg(&in4[i]);
        const __nv_bfloat162 lo = __floats2bfloat162_rn(v.x, v.y);
        const __nv_bfloat162 hi = __floats2bfloat162_rn(v.z, v.w);
        uint2 st;
        st.x = *reinterpret_cast<const unsigned int*>(&lo);
        st.y = *reinterpret_cast<const unsigned int*>(&hi);
        ob[i] = st;
    }
}

// One sample's dot: 4 x LDG.128 bf16 input vs packed f32x2 weight regs.
__device__ __forceinline__ float sample_dot(const u64* __restrict__ wp,
                                            const __nv_bfloat16* __restrict__ xrow,
                                            int lane)
{
    const uint4* xp = reinterpret_cast<const uint4*>(xrow);
    uint4 xr[4];
    #pragma unroll
    for (int k = 0; k < 4; k++) xr[k] = __ldg(&xp[lane + 32 * k]);

    u64 a0 = 0, a1 = 0;        // two packed accumulators (zero = 0.0f pair)
    #pragma unroll
    for (int k = 0; k < 4; k++) {
        ffma2(a0, wp[4 * k + 0], cvt2(xr[k].x));
        ffma2(a1, wp[4 * k + 1], cvt2(xr[k].y));
        ffma2(a0, wp[4 * k + 2], cvt2(xr[k].z));
        ffma2(a1, wp[4 * k + 3], cvt2(xr[k].w));
    }
    float d = unpack_sum(a0) + unpack_sum(a1);
    #pragma unroll
    for (int o = 16; o; o >>= 1) d += __shfl_xor_sync(0xffffffffu, d, o);
    return d;
}

// ------- B: main - warp per weight row, loss terms, full reduction --------
__global__ __launch_bounds__(DOT_BLOCK, 8) void dot_kernel(
    const float* __restrict__ weight,
    const float* __restrict__ bias,
    const float* __restrict__ noise,
    float*       __restrict__ out,
    int V, int N)
{
    __shared__ double s_dsum[DOT_BLOCK / 32];
    __shared__ bool   s_is_last;

    const int lane   = threadIdx.x & 31;
    const int wid    = threadIdx.x >> 5;
    const int warpg  = (blockIdx.x * blockDim.x + threadIdx.x) >> 5;
    const int nwarps = (gridDim.x * blockDim.x) >> 5;

    float acc = 0.0f;                       // lane-0 loss accumulator

    for (int r = warpg; r < V; r += nwarps) {
        int c = __ldg(&g_cnt[r]);
        if (c == 0) continue;
        if (c > CAP) c = CAP;
        const int cmain = (c < 32) ? c : 32;

        // Lane-parallel preload of this row's bucket entries.
        const int e_lane = (lane < cmain)
            ? __ldg(&g_bucket[r * CAP + lane]) : 0;

        // Load the full 4 KB weight row, grouped 8 elements per lane-step:
        // lane covers f32 elements [8*(lane+32k), 8*(lane+32k)+8).
        const float4* w4 = reinterpret_cast<const float4*>(
            weight + (size_t)r * EDIM);
        u64 wp[16];
        #pragma unroll
        for (int k = 0; k < 4; k++) {
            const float4 wa = __ldg(&w4[2 * (lane + 32 * k) + 0]);
            const float4 wb = __ldg(&w4[2 * (lane + 32 * k) + 1]);
            wp[4 * k + 0] = pack2(wa.x, wa.y);
            wp[4 * k + 1] = pack2(wa.z, wa.w);
            wp[4 * k + 2] = pack2(wb.x, wb.y);
            wp[4 * k + 3] = pack2(wb.z, wb.w);
        }

        const float brow = __ldg(&bias[r]);
        const float kp   = (float)KNOISE * __ldg(&noise[r]);

        for (int s = 0; s < cmain; s++) {
            const int e = __shfl_sync(0xffffffffu, e_lane, s);
            const int n = e / NCOLS;
            const float d = sample_dot(wp, g_xbf + (size_t)n * EDIM, lane);
            if (lane == 0) {
                const float p   = expf(d + brow - NORM_TERM);
                const bool  isT = (e - n * NCOLS) == 0;     // j == 0
                acc += logf((isT ? p : kp) / (p + kp));
            }
        }
        // Extremely rare tail (count > 32).
        for (int s = 32; s < c; s++) {
            const int e = __ldg(&g_bucket[r * CAP + s]);
            const int n = e / NCOLS;
            const float d = sample_dot(wp, g_xbf + (size_t)n * EDIM, lane);
            if (lane == 0) {
                const float p   = expf(d + brow - NORM_TERM);
                const bool  isT = (e - n * NCOLS) == 0;
                acc += logf((isT ? p : kp) / (p + kp));
            }
        }

        if (lane == 0) g_cnt[r] = 0;        // ready for next replay's scatter
    }

    // Block reduction (lane 0s hold partial sums) -> global atomic.
    if (lane == 0) s_dsum[wid] = (double)acc;
    __syncthreads();
    if (wid == 0) {
        double t = (lane < DOT_BLOCK / 32) ? s_dsum[lane] : 0.0;
        #pragma unroll
        for (int o = (DOT_BLOCK / 64); o; o >>= 1)
            t += __shfl_xor_sync(0xffffffffu, t, o);
        if (lane == 0) atomicAdd(&g_acc, t);
    }

    // Completion ticket: last block writes the scalar and resets state.
    if (threadIdx.x == 0) {
        __threadfence();
        unsigned int prev = atomicAdd(&g_done, 1u);
        s_is_last = (prev == gridDim.x - 1);
    }
    __syncthreads();

    if (s_is_last && threadIdx.x == 0) {
        double t;
        asm volatile("ld.global.cg.f64 %0, [%1];" : "=d"(t) : "l"(&g_acc));
        out[0] = (float)(-t / (double)N);
        g_acc  = 0.0;                       // reset for graph replay
        __threadfence();
        g_done = 0u;
    }
}

extern "C" void kernel_launch(void* const* d_in, const int* in_sizes, int n_in,
                              void* d_out, int out_size) {
    const float* input         = (const float*)d_in[0];
    const int*   target        = (const int*)  d_in[1];
    const int*   noise_samples = (const int*)  d_in[2];
    const float* noise         = (const float*)d_in[3];
    const float* weight        = (const float*)d_in[4];
    const float* bias          = (const float*)d_in[5];
    float* out = (float*)d_out;

    const int N = in_sizes[1];   // examples
    const int V = in_sizes[3];   // vocab size

    prep_kernel<<<1024, 256>>>(input, target, noise_samples, N);
    dot_kernel<<<DOT_GRID, DOT_BLOCK>>>(weight, bias, noise, out, V, N);
}